// round 13
// baseline (speedup 1.0000x reference)
#include <cuda_runtime.h>
#include <cstdint>

// ---------------------------------------------------------------------------
// MLGRUCell via exact bf16 tensor-core path (HMMA m16n8k16):
//   quantized activations are exact ints in [-127,127]; sign weights {-1,0,+1}
//   -> both exact in bf16, K=128 dot exact in fp32 accum.
// Gates: sigmoid(y)=0.5*tanh(y/2)+0.5 via tanh.approx.f32.
// R13: B fragment table lives in SMEM (96KB, copied once per block) -> B loads
//      are 29-cyc LDS instead of ~250-cyc L2 LDG. 256-thread blocks, 256 rows,
//      one block per SM; register cap lifted.
// ---------------------------------------------------------------------------

// B fragments bf16: [mat(3)][ch(8)][kt(8)][lane(32)] -> uint4
//  .x/.y = b0/b1 of even (permuted) tile, .z/.w = odd tile.
//  Tile n-index j maps to actual column: ch*16 + (j>>1)*4 + 2*s + (j&1).
__device__ uint4 g_wfrag[3 * 8 * 8 * 32];

__device__ __forceinline__ unsigned sgn_bf16(float v) {
    return v > 0.f ? 0x3F80u : (v < 0.f ? 0xBF80u : 0u);
}

__global__ void prep_kernel(const float* __restrict__ Wf,
                            const float* __restrict__ Wc,
                            const float* __restrict__ Wg) {
    int idx = blockIdx.x * blockDim.x + threadIdx.x;
    if (idx >= 3 * 8 * 8 * 32) return;
    int lane = idx & 31;
    int kt   = (idx >> 5) & 7;
    int ch   = (idx >> 8) & 7;
    int mat  = idx >> 11;
    const float* W = (mat == 0) ? Wf : ((mat == 1) ? Wc : Wg);
    int g = lane >> 2, tig = lane & 3;
    int ne = ch * 16 + (g >> 1) * 4 + (g & 1);      // s=0
    int no = ne + 2;                                 // s=1
    int k0 = kt * 16 + tig * 2;
    uint4 r;
    // B[k][n] = sign(W[n][k]); W row-major [hidden=128][in=128]
    r.x = sgn_bf16(W[ne * 128 + k0])     | (sgn_bf16(W[ne * 128 + k0 + 1]) << 16);
    r.y = sgn_bf16(W[ne * 128 + k0 + 8]) | (sgn_bf16(W[ne * 128 + k0 + 9]) << 16);
    r.z = sgn_bf16(W[no * 128 + k0])     | (sgn_bf16(W[no * 128 + k0 + 1]) << 16);
    r.w = sgn_bf16(W[no * 128 + k0 + 8]) | (sgn_bf16(W[no * 128 + k0 + 9]) << 16);
    g_wfrag[idx] = r;
}

#define MMA_OP(D, A, b0, b1)                                                   \
    asm volatile(                                                              \
        "mma.sync.aligned.m16n8k16.row.col.f32.bf16.bf16.f32 "                 \
        "{%0,%1,%2,%3}, {%4,%5,%6,%7}, {%8,%9}, {%0,%1,%2,%3};\n"              \
        : "+f"(D[0]), "+f"(D[1]), "+f"(D[2]), "+f"(D[3])                       \
        : "r"(A.x), "r"(A.y), "r"(A.z), "r"(A.w), "r"(b0), "r"(b1))

__device__ __forceinline__ float tanh_ap(float x) {
    float y;
    asm("tanh.approx.f32 %0, %1;" : "=f"(y) : "f"(x));
    return y;
}

// ---- packed f32x2 helpers (sm_100+) ----
typedef unsigned long long u64t;
__device__ __forceinline__ u64t pk2(float x, float y) {
    u64t r; asm("mov.b64 %0, {%1, %2};" : "=l"(r) : "f"(x), "f"(y)); return r;
}
__device__ __forceinline__ float2 up2(u64t v) {
    float2 r; asm("mov.b64 {%0, %1}, %2;" : "=f"(r.x), "=f"(r.y) : "l"(v));
    return r;
}
__device__ __forceinline__ u64t fma2_(u64t a, u64t b, u64t c) {
    u64t d; asm("fma.rn.f32x2 %0, %1, %2, %3;" : "=l"(d) : "l"(a), "l"(b), "l"(c));
    return d;
}
__device__ __forceinline__ u64t add2_(u64t a, u64t b) {
    u64t d; asm("add.rn.f32x2 %0, %1, %2;" : "=l"(d) : "l"(a), "l"(b)); return d;
}
__device__ __forceinline__ u64t mul2_(u64t a, u64t b) {
    u64t d; asm("mul.rn.f32x2 %0, %1, %2;" : "=l"(d) : "l"(a), "l"(b)); return d;
}
__device__ __forceinline__ u64t abs2_(u64t a) {
    u64t d; asm("and.b64 %0, %1, %2;" : "=l"(d)
                : "l"(a), "l"(0x7FFFFFFF7FFFFFFFULL)); return d;
}

// SMEM layout (bytes)
#define SM_B_OFF     0                 // 6144 uint4 = 98304
#define SM_Q_OFF     98304             // qfrag [16][8][32] uint4 = 65536
#define SM_BIAS_OFF  163840            // 3*128 f32 = 1536
#define SM_SINV_OFF  165376            // 256 f32 = 1024
#define SM_TOTAL     166400

__global__ __launch_bounds__(256, 1) void mlgru_kernel(
    const float* __restrict__ x, const float* __restrict__ hprev,
    const float* __restrict__ bf_, const float* __restrict__ bc_,
    const float* __restrict__ bg_, float* __restrict__ out, int half) {
    extern __shared__ char smem[];
    uint4* smB = (uint4*)(smem + SM_B_OFF);
    // qfrag: [mtile(16)][ktile(8)][lane(32)] -> uint4
    uint4 (*qfrag)[8][32] = (uint4 (*)[8][32])(smem + SM_Q_OFF);
    float* bias_sh = (float*)(smem + SM_BIAS_OFF);
    float* sinv    = (float*)(smem + SM_SINV_OFF);

    const int tid = threadIdx.x;
    const int w = tid >> 5, l = tid & 31;
    const int rowBlock = blockIdx.x * 256;

    // ---- copy B table into smem (96KB, L2-hot after first block) ----
    #pragma unroll
    for (int i = 0; i < 24; i++) smB[tid + 256 * i] = g_wfrag[tid + 256 * i];

    if (tid < 128) {
        bias_sh[tid]       = 0.5f * bf_[tid];
        bias_sh[128 + tid] = 0.5f * bc_[tid];
        bias_sh[256 + tid] = 0.5f * bg_[tid];
    }

    // ------------------- Phase 1: layernorm + quant (packed) ----------------
    // warp w owns rows w*32..w*32+31; 4 rows/iter; lane l: row (l>>3),
    // cols (l&7)*4 + 32j.
    {
        const int clb = (l & 7) * 4;
        #pragma unroll 2
        for (int it = 0; it < 8; it++) {
            const int r = w * 32 + it * 4 + (l >> 3);      // block-local row
            const float4* xr = (const float4*)(x + (size_t)(rowBlock + r) * 128);
            u64t vp[8];
            #pragma unroll
            for (int j = 0; j < 4; j++) {
                const float4 v = xr[(clb >> 2) + 8 * j];
                vp[2 * j]     = pk2(v.x, v.y);
                vp[2 * j + 1] = pk2(v.z, v.w);
            }

            u64t s1p = add2_(add2_(add2_(vp[0], vp[1]), add2_(vp[2], vp[3])),
                             add2_(add2_(vp[4], vp[5]), add2_(vp[6], vp[7])));
            u64t s2p = mul2_(vp[0], vp[0]);
            #pragma unroll
            for (int k = 1; k < 8; k++) s2p = fma2_(vp[k], vp[k], s2p);
            float2 t1 = up2(s1p), t2 = up2(s2p);
            float s1 = t1.x + t1.y, s2 = t2.x + t2.y;

            #pragma unroll
            for (int m = 1; m <= 4; m <<= 1) {
                s1 += __shfl_xor_sync(0xffffffffu, s1, m);
                s2 += __shfl_xor_sync(0xffffffffu, s2, m);
            }
            const float mean = s1 * (1.f / 128.f);
            const float var  = s2 * (1.f / 128.f) - mean * mean;
            const float rstd = rsqrtf(var + 1e-8f);

            const u64t rs2 = pk2(rstd, rstd);
            const u64t nm2 = pk2(-mean * rstd, -mean * rstd);
            float mx = 0.f;
            #pragma unroll
            for (int k = 0; k < 8; k++) {
                const float2 a = up2(abs2_(fma2_(vp[k], rs2, nm2)));
                mx = fmaxf(mx, fmaxf(a.x, a.y));
            }
            #pragma unroll
            for (int m = 1; m <= 4; m <<= 1)
                mx = fmaxf(mx, __shfl_xor_sync(0xffffffffu, mx, m));

            const float s = __fdividef(127.f, mx);
            if ((l & 7) == 0) sinv[r] = 0.5f * mx * (1.f / 127.f);

            // fused quant: q = rint((v-mean)*rstd*s); |q|<=127 by construction.
            const float aa = rstd * s;
            const u64t aa2 = pk2(aa, aa);
            const u64t bb2 = pk2(-mean * aa, -mean * aa);

            const int mt = r >> 4, g8 = r & 7, hi2 = (r >> 3) & 1;
            #pragma unroll
            for (int j = 0; j < 4; j++) {
                #pragma unroll
                for (int p = 0; p < 2; p++) {
                    const float2 q = up2(fma2_(vp[2 * j + p], aa2, bb2));
                    // bf16 of small ints == high 16 bits of fp32 (exact)
                    const unsigned u = __byte_perm(
                        __float_as_uint(rintf(q.x)),
                        __float_as_uint(rintf(q.y)), 0x7632);
                    const int c0  = clb + 32 * j + 2 * p;
                    const int kt  = c0 >> 4;
                    const int tg  = (c0 >> 1) & 3;
                    const int khi = (c0 >> 3) & 1;
                    ((unsigned*)&qfrag[mt][kt][(g8 << 2) | tg])[hi2 | (khi << 1)] = u;
                }
            }
        }
    }
    __syncthreads();

    // ------------------- Phase 2: 3 ternary MMAs + gates -------------------
    const int g = l >> 2, tig = l & 3;

    float sih[2][2];
    #pragma unroll
    for (int mt = 0; mt < 2; mt++)
        #pragma unroll
        for (int rh = 0; rh < 2; rh++)
            sih[mt][rh] = sinv[w * 32 + mt * 16 + g + rh * 8];

    const uint4* wbase = smB + l;
    const int rbase = rowBlock + w * 32 + g;   // + mt*16 + rh*8

    #pragma unroll 1
    for (int ch = 0; ch < 8; ch++) {    // 16 output columns per chunk
        const int cbase = ch * 16 + tig * 4;   // 4 contiguous cols per thread

        // ---- prefetch hprev (float4 per (mt,rh)) ----
        float4 hp[2][2];
        #pragma unroll
        for (int mt = 0; mt < 2; mt++)
            #pragma unroll
            for (int rh = 0; rh < 2; rh++)
                hp[mt][rh] = *(const float4*)(hprev +
                    (size_t)(rbase + mt * 16 + rh * 8) * 128 + cbase);

        // acc[mat][mt][tile][4]
        float acc[3][2][2][4];
        #pragma unroll
        for (int m_ = 0; m_ < 3; m_++)
            #pragma unroll
            for (int a_ = 0; a_ < 2; a_++)
                #pragma unroll
                for (int t_ = 0; t_ < 2; t_++)
                    #pragma unroll
                    for (int e_ = 0; e_ < 4; e_++) acc[m_][a_][t_][e_] = 0.f;

        #pragma unroll
        for (int kt = 0; kt < 8; kt++) {
            const uint4 A0 = qfrag[2 * w][kt][l];
            const uint4 A1 = qfrag[2 * w + 1][kt][l];
            #pragma unroll
            for (int mat = 0; mat < 3; mat++) {
                const uint4 Bv = wbase[((mat * 8 + ch) * 8 + kt) * 32];
                MMA_OP(acc[mat][0][0], A0, Bv.x, Bv.y);
                MMA_OP(acc[mat][1][0], A1, Bv.x, Bv.y);
                MMA_OP(acc[mat][0][1], A0, Bv.z, Bv.w);
                MMA_OP(acc[mat][1][1], A1, Bv.z, Bv.w);
            }
        }

        // ---- epilogue: 4 contiguous cols/thread, float4 stores ----
        const float4 bF = *(const float4*)&bias_sh[cbase];
        const float4 bC = *(const float4*)&bias_sh[128 + cbase];
        const float4 bG = *(const float4*)&bias_sh[256 + cbase];
        const float bFv[4] = {bF.x, bF.y, bF.z, bF.w};
        const float bCv[4] = {bC.x, bC.y, bC.z, bC.w};
        const float bGv[4] = {bG.x, bG.y, bG.z, bG.w};

        #pragma unroll
        for (int mt = 0; mt < 2; mt++) {
            #pragma unroll
            for (int rh = 0; rh < 2; rh++) {
                const int row = rbase + mt * 16 + rh * 8;
                const float si = sih[mt][rh];
                const float hpv[4] = {hp[mt][rh].x, hp[mt][rh].y,
                                      hp[mt][rh].z, hp[mt][rh].w};
                float ov[4], hv[4];
                #pragma unroll
                for (int c = 0; c < 4; c++) {
                    const int t_ = c >> 1, e_ = rh * 2 + (c & 1);
                    const float zf = fmaf(acc[0][mt][t_][e_], si, bFv[c]);
                    const float zc = fmaf(acc[1][mt][t_][e_], si, bCv[c]);
                    const float zg = fmaf(acc[2][mt][t_][e_], si, bGv[c]);
                    const float f  = fmaf(0.5f, tanh_ap(zf), 0.5f);
                    const float gg = fmaf(0.5f, tanh_ap(zg), 0.5f);
                    const float sc = fmaf(0.5f, tanh_ap(zc), 0.5f);
                    const float cv = (zc + zc) * sc;      // silu
                    const float h  = fmaf(f, hpv[c] - cv, cv);
                    hv[c] = h;
                    ov[c] = gg * h;
                }
                *(float4*)(out + (size_t)row * 128 + cbase) =
                    make_float4(ov[0], ov[1], ov[2], ov[3]);
                *(float4*)(out + (size_t)half + (size_t)row * 128 + cbase) =
                    make_float4(hv[0], hv[1], hv[2], hv[3]);
            }
        }
    }
}

extern "C" void kernel_launch(void* const* d_in, const int* in_sizes, int n_in,
                              void* d_out, int out_size) {
    const float* x  = (const float*)d_in[0];
    const float* h  = (const float*)d_in[1];
    const float* Wf = (const float*)d_in[2];
    const float* Wc = (const float*)d_in[3];
    const float* Wg = (const float*)d_in[4];
    const float* bf = (const float*)d_in[5];
    const float* bc = (const float*)d_in[6];
    const float* bg = (const float*)d_in[7];
    float* out = (float*)d_out;

    cudaFuncSetAttribute(mlgru_kernel,
                         cudaFuncAttributeMaxDynamicSharedMemorySize, SM_TOTAL);

    prep_kernel<<<48, 128>>>(Wf, Wc, Wg);

    const int rows = in_sizes[0] / 128;      // 262144
    const int blocks = rows / 256;           // 1024
    const int half = out_size / 2;
    mlgru_kernel<<<blocks, 256, SM_TOTAL>>>(x, h, bf, bc, bg, out, half);
}

// round 14
// speedup vs baseline: 1.1253x; 1.1253x over previous
#include <cuda_runtime.h>
#include <cstdint>

// ---------------------------------------------------------------------------
// MLGRUCell via exact bf16 tensor-core path (HMMA m16n8k16):
//   quantized activations are exact ints in [-127,127]; sign weights {-1,0,+1}
//   -> both exact in bf16, K=128 dot exact in fp32 accum.
// Gates: sigmoid(y)=0.5*tanh(y/2)+0.5 via tanh.approx.f32.
// B packed with a column permutation so each thread owns 4 contiguous output
// columns -> float4 epilogue.
// R14: phase-1 rebuilt as 4-lane row reductions (24 shuffles/task, MLP_p1=8),
//      dequant scales stay in registers, zero block barriers (warp-local).
// ---------------------------------------------------------------------------

// B fragments bf16: [mat(3)][ch(8)][kt(8)][lane(32)] -> uint4
__device__ uint4 g_wfrag[3 * 8 * 8 * 32];

__device__ __forceinline__ unsigned sgn_bf16(float v) {
    return v > 0.f ? 0x3F80u : (v < 0.f ? 0xBF80u : 0u);
}

__global__ void prep_kernel(const float* __restrict__ Wf,
                            const float* __restrict__ Wc,
                            const float* __restrict__ Wg) {
    int idx = blockIdx.x * blockDim.x + threadIdx.x;
    if (idx >= 3 * 8 * 8 * 32) return;
    int lane = idx & 31;
    int kt   = (idx >> 5) & 7;
    int ch   = (idx >> 8) & 7;
    int mat  = idx >> 11;
    const float* W = (mat == 0) ? Wf : ((mat == 1) ? Wc : Wg);
    int g = lane >> 2, tig = lane & 3;
    int ne = ch * 16 + (g >> 1) * 4 + (g & 1);      // s=0
    int no = ne + 2;                                 // s=1
    int k0 = kt * 16 + tig * 2;
    uint4 r;
    // B[k][n] = sign(W[n][k]); W row-major [hidden=128][in=128]
    r.x = sgn_bf16(W[ne * 128 + k0])     | (sgn_bf16(W[ne * 128 + k0 + 1]) << 16);
    r.y = sgn_bf16(W[ne * 128 + k0 + 8]) | (sgn_bf16(W[ne * 128 + k0 + 9]) << 16);
    r.z = sgn_bf16(W[no * 128 + k0])     | (sgn_bf16(W[no * 128 + k0 + 1]) << 16);
    r.w = sgn_bf16(W[no * 128 + k0 + 8]) | (sgn_bf16(W[no * 128 + k0 + 9]) << 16);
    g_wfrag[idx] = r;
}

#define MMA_OP(D, A, b0, b1)                                                   \
    asm volatile(                                                              \
        "mma.sync.aligned.m16n8k16.row.col.f32.bf16.bf16.f32 "                 \
        "{%0,%1,%2,%3}, {%4,%5,%6,%7}, {%8,%9}, {%0,%1,%2,%3};\n"              \
        : "+f"(D[0]), "+f"(D[1]), "+f"(D[2]), "+f"(D[3])                       \
        : "r"(A.x), "r"(A.y), "r"(A.z), "r"(A.w), "r"(b0), "r"(b1))

__device__ __forceinline__ float tanh_ap(float x) {
    float y;
    asm("tanh.approx.f32 %0, %1;" : "=f"(y) : "f"(x));
    return y;
}

// ---- packed f32x2 helpers (sm_100+) ----
typedef unsigned long long u64t;
__device__ __forceinline__ u64t pk2(float x, float y) {
    u64t r; asm("mov.b64 %0, {%1, %2};" : "=l"(r) : "f"(x), "f"(y)); return r;
}
__device__ __forceinline__ float2 up2(u64t v) {
    float2 r; asm("mov.b64 {%0, %1}, %2;" : "=f"(r.x), "=f"(r.y) : "l"(v));
    return r;
}
__device__ __forceinline__ u64t fma2_(u64t a, u64t b, u64t c) {
    u64t d; asm("fma.rn.f32x2 %0, %1, %2, %3;" : "=l"(d) : "l"(a), "l"(b), "l"(c));
    return d;
}
__device__ __forceinline__ u64t add2_(u64t a, u64t b) {
    u64t d; asm("add.rn.f32x2 %0, %1, %2;" : "=l"(d) : "l"(a), "l"(b)); return d;
}
__device__ __forceinline__ u64t mul2_(u64t a, u64t b) {
    u64t d; asm("mul.rn.f32x2 %0, %1, %2;" : "=l"(d) : "l"(a), "l"(b)); return d;
}
__device__ __forceinline__ u64t abs2_(u64t a) {
    u64t d; asm("and.b64 %0, %1, %2;" : "=l"(d)
                : "l"(a), "l"(0x7FFFFFFF7FFFFFFFULL)); return d;
}

__global__ __launch_bounds__(128, 4) void mlgru_kernel(
    const float* __restrict__ x, const float* __restrict__ hprev,
    const float* __restrict__ bf_, const float* __restrict__ bc_,
    const float* __restrict__ bg_, float* __restrict__ out, int half) {
    // A fragments: [mtile(8)][ktile(8)][lane(32)] -> uint4 (a0..a3). Warp w
    // only touches mtiles 2w, 2w+1 -> strictly warp-local, no block barrier.
    __shared__ uint4 qfrag[8][8][32];

    const int tid = threadIdx.x;
    const int w = tid >> 5, l = tid & 31;
    const int q4 = l & 3;          // column group (phase 1)
    const int rg = l >> 2;         // row-in-octet (phase 1), == g (phase 2)
    const int rowBlock = blockIdx.x * 128;

    // sih[it]: 0.5*(maxabs/127) of local row it*8 + rg  (it = 2*mt + rh)
    float sih[4];

    // ------------- Phase 1: layernorm + quant (4-lane reductions) ----------
    // iter it: lane handles row w*32 + it*8 + rg, cols 16j + 4*q4 (j=0..7).
    {
        #pragma unroll 1
        for (int it = 0; it < 4; it++) {
            const int rl = w * 32 + it * 8 + rg;          // block-local row
            const float4* xr = (const float4*)(x + (size_t)(rowBlock + rl) * 128);
            u64t vp[16];
            #pragma unroll
            for (int j = 0; j < 8; j++) {
                const float4 v = xr[4 * j + q4];
                vp[2 * j]     = pk2(v.x, v.y);
                vp[2 * j + 1] = pk2(v.z, v.w);
            }

            // packed sum / sum-of-squares over 32 local elements
            u64t s1p = add2_(vp[0], vp[1]);
            #pragma unroll
            for (int k = 2; k < 16; k++) s1p = add2_(s1p, vp[k]);
            u64t s2p = mul2_(vp[0], vp[0]);
            #pragma unroll
            for (int k = 1; k < 16; k++) s2p = fma2_(vp[k], vp[k], s2p);
            float2 t1 = up2(s1p), t2 = up2(s2p);
            float s1 = t1.x + t1.y, s2 = t2.x + t2.y;

            // 4-lane butterfly (masks 1, 2)
            #pragma unroll
            for (int m = 1; m <= 2; m <<= 1) {
                s1 += __shfl_xor_sync(0xffffffffu, s1, m);
                s2 += __shfl_xor_sync(0xffffffffu, s2, m);
            }
            const float mean = s1 * (1.f / 128.f);
            const float var  = s2 * (1.f / 128.f) - mean * mean;
            const float rstd = rsqrtf(var + 1e-8f);

            const u64t rs2 = pk2(rstd, rstd);
            const u64t nm2 = pk2(-mean * rstd, -mean * rstd);
            float mx = 0.f;
            #pragma unroll
            for (int k = 0; k < 16; k++) {
                const float2 a = up2(abs2_(fma2_(vp[k], rs2, nm2)));
                mx = fmaxf(mx, fmaxf(a.x, a.y));
            }
            #pragma unroll
            for (int m = 1; m <= 2; m <<= 1)
                mx = fmaxf(mx, __shfl_xor_sync(0xffffffffu, mx, m));

            const float s = __fdividef(127.f, mx);
            sih[it] = 0.5f * mx * (1.f / 127.f);   // register handoff to P2

            // fused quant: q = rint((v-mean)*rstd*s); |q|<=127 by construction
            const float aa = rstd * s;
            const u64t aa2 = pk2(aa, aa);
            const u64t bb2 = pk2(-mean * aa, -mean * aa);

            const int mt = rl >> 4, g8 = rl & 7, hi2 = (rl >> 3) & 1;
            #pragma unroll
            for (int j = 0; j < 8; j++) {        // kt == j
                #pragma unroll
                for (int p = 0; p < 2; p++) {
                    const float2 qv = up2(fma2_(vp[2 * j + p], aa2, bb2));
                    // bf16 of small ints == high 16 bits of fp32 (exact)
                    const unsigned u = __byte_perm(
                        __float_as_uint(rintf(qv.x)),
                        __float_as_uint(rintf(qv.y)), 0x7632);
                    const int idx8 = 2 * q4 + p;          // 0..7
                    const int tg   = idx8 & 3;
                    const int khi  = idx8 >> 2;
                    ((unsigned*)&qfrag[mt][j][(g8 << 2) | tg])[hi2 | (khi << 1)] = u;
                }
            }
        }
    }
    __syncwarp();

    // ------------------- Phase 2: 3 ternary MMAs + gates -------------------
    const int g = rg, tig = q4;

    const uint4* wbase = g_wfrag + l;
    const int rbase = rowBlock + w * 32 + g;   // + mt*16 + rh*8

    #pragma unroll 1
    for (int ch = 0; ch < 8; ch++) {    // 16 output columns per chunk
        const int cbase = ch * 16 + tig * 4;   // 4 contiguous cols per thread

        // ---- prefetch hprev (float4 per (mt,rh)) ----
        float4 hp[2][2];
        #pragma unroll
        for (int mt = 0; mt < 2; mt++)
            #pragma unroll
            for (int rh = 0; rh < 2; rh++)
                hp[mt][rh] = *(const float4*)(hprev +
                    (size_t)(rbase + mt * 16 + rh * 8) * 128 + cbase);

        // acc[mat][mt][tile][4]
        float acc[3][2][2][4];
        #pragma unroll
        for (int m_ = 0; m_ < 3; m_++)
            #pragma unroll
            for (int a_ = 0; a_ < 2; a_++)
                #pragma unroll
                for (int t_ = 0; t_ < 2; t_++)
                    #pragma unroll
                    for (int e_ = 0; e_ < 4; e_++) acc[m_][a_][t_][e_] = 0.f;

        #pragma unroll
        for (int kt = 0; kt < 8; kt++) {
            const uint4 A0 = qfrag[2 * w][kt][l];
            const uint4 A1 = qfrag[2 * w + 1][kt][l];
            #pragma unroll
            for (int mat = 0; mat < 3; mat++) {
                const uint4 Bv = wbase[((mat * 8 + ch) * 8 + kt) * 32];
                MMA_OP(acc[mat][0][0], A0, Bv.x, Bv.y);
                MMA_OP(acc[mat][1][0], A1, Bv.x, Bv.y);
                MMA_OP(acc[mat][0][1], A0, Bv.z, Bv.w);
                MMA_OP(acc[mat][1][1], A1, Bv.z, Bv.w);
            }
        }

        // ---- epilogue: 4 contiguous cols/thread, float4 stores ----
        const float4 bF = __ldg((const float4*)(bf_ + cbase));
        const float4 bC = __ldg((const float4*)(bc_ + cbase));
        const float4 bG = __ldg((const float4*)(bg_ + cbase));
        const float bFv[4] = {0.5f*bF.x, 0.5f*bF.y, 0.5f*bF.z, 0.5f*bF.w};
        const float bCv[4] = {0.5f*bC.x, 0.5f*bC.y, 0.5f*bC.z, 0.5f*bC.w};
        const float bGv[4] = {0.5f*bG.x, 0.5f*bG.y, 0.5f*bG.z, 0.5f*bG.w};

        #pragma unroll
        for (int mt = 0; mt < 2; mt++) {
            #pragma unroll
            for (int rh = 0; rh < 2; rh++) {
                const int row = rbase + mt * 16 + rh * 8;
                const float si = sih[2 * mt + rh];
                const float hpv[4] = {hp[mt][rh].x, hp[mt][rh].y,
                                      hp[mt][rh].z, hp[mt][rh].w};
                float ov[4], hv[4];
                #pragma unroll
                for (int c = 0; c < 4; c++) {
                    const int t_ = c >> 1, e_ = rh * 2 + (c & 1);
                    const float zf = fmaf(acc[0][mt][t_][e_], si, bFv[c]);
                    const float zc = fmaf(acc[1][mt][t_][e_], si, bCv[c]);
                    const float zg = fmaf(acc[2][mt][t_][e_], si, bGv[c]);
                    const float f  = fmaf(0.5f, tanh_ap(zf), 0.5f);
                    const float gg = fmaf(0.5f, tanh_ap(zg), 0.5f);
                    const float sc = fmaf(0.5f, tanh_ap(zc), 0.5f);
                    const float cv = (zc + zc) * sc;      // silu
                    const float h  = fmaf(f, hpv[c] - cv, cv);
                    hv[c] = h;
                    ov[c] = gg * h;
                }
                *(float4*)(out + (size_t)row * 128 + cbase) =
                    make_float4(ov[0], ov[1], ov[2], ov[3]);
                *(float4*)(out + (size_t)half + (size_t)row * 128 + cbase) =
                    make_float4(hv[0], hv[1], hv[2], hv[3]);
            }
        }
    }
}

extern "C" void kernel_launch(void* const* d_in, const int* in_sizes, int n_in,
                              void* d_out, int out_size) {
    const float* x  = (const float*)d_in[0];
    const float* h  = (const float*)d_in[1];
    const float* Wf = (const float*)d_in[2];
    const float* Wc = (const float*)d_in[3];
    const float* Wg = (const float*)d_in[4];
    const float* bf = (const float*)d_in[5];
    const float* bc = (const float*)d_in[6];
    const float* bg = (const float*)d_in[7];
    float* out = (float*)d_out;

    prep_kernel<<<48, 128>>>(Wf, Wc, Wg);

    const int rows = in_sizes[0] / 128;      // 262144
    const int blocks = rows / 128;           // 2048
    const int half = out_size / 2;
    mlgru_kernel<<<blocks, 128>>>(x, h, bf, bc, bg, out, half);
}

// round 15
// speedup vs baseline: 1.2532x; 1.1137x over previous
#include <cuda_runtime.h>
#include <cstdint>

// ---------------------------------------------------------------------------
// MLGRUCell via exact bf16 tensor-core path (HMMA m16n8k16):
//   quantized activations are exact ints in [-127,127]; sign weights {-1,0,+1}
//   -> both exact in bf16, K=128 dot exact in fp32 accum.
// Gates: sigmoid(y)=0.5*tanh(y/2)+0.5 via tanh.approx.f32.
// B packed with a column permutation so each thread owns 4 contiguous output
// columns -> float4 epilogue.
// R15: B fragments staged into SMEM via cp.async double-buffer (6KB units,
//      copy of unit u+1 overlaps MMAs of unit u) -> B reads are 29-cyc LDS,
//      B global traffic 4x down, occupancy kept at 4 blocks/SM.
// ---------------------------------------------------------------------------

// B fragments bf16: [mat(3)][ch(8)][kt(8)][lane(32)] -> uint4
__device__ uint4 g_wfrag[3 * 8 * 8 * 32];

__device__ __forceinline__ unsigned sgn_bf16(float v) {
    return v > 0.f ? 0x3F80u : (v < 0.f ? 0xBF80u : 0u);
}

__global__ void prep_kernel(const float* __restrict__ Wf,
                            const float* __restrict__ Wc,
                            const float* __restrict__ Wg) {
    int idx = blockIdx.x * blockDim.x + threadIdx.x;
    if (idx >= 3 * 8 * 8 * 32) return;
    int lane = idx & 31;
    int kt   = (idx >> 5) & 7;
    int ch   = (idx >> 8) & 7;
    int mat  = idx >> 11;
    const float* W = (mat == 0) ? Wf : ((mat == 1) ? Wc : Wg);
    int g = lane >> 2, tig = lane & 3;
    int ne = ch * 16 + (g >> 1) * 4 + (g & 1);      // s=0
    int no = ne + 2;                                 // s=1
    int k0 = kt * 16 + tig * 2;
    uint4 r;
    // B[k][n] = sign(W[n][k]); W row-major [hidden=128][in=128]
    r.x = sgn_bf16(W[ne * 128 + k0])     | (sgn_bf16(W[ne * 128 + k0 + 1]) << 16);
    r.y = sgn_bf16(W[ne * 128 + k0 + 8]) | (sgn_bf16(W[ne * 128 + k0 + 9]) << 16);
    r.z = sgn_bf16(W[no * 128 + k0])     | (sgn_bf16(W[no * 128 + k0 + 1]) << 16);
    r.w = sgn_bf16(W[no * 128 + k0 + 8]) | (sgn_bf16(W[no * 128 + k0 + 9]) << 16);
    g_wfrag[idx] = r;
}

#define MMA_OP(D, A, b0, b1)                                                   \
    asm volatile(                                                              \
        "mma.sync.aligned.m16n8k16.row.col.f32.bf16.bf16.f32 "                 \
        "{%0,%1,%2,%3}, {%4,%5,%6,%7}, {%8,%9}, {%0,%1,%2,%3};\n"              \
        : "+f"(D[0]), "+f"(D[1]), "+f"(D[2]), "+f"(D[3])                       \
        : "r"(A.x), "r"(A.y), "r"(A.z), "r"(A.w), "r"(b0), "r"(b1))

__device__ __forceinline__ float tanh_ap(float x) {
    float y;
    asm("tanh.approx.f32 %0, %1;" : "=f"(y) : "f"(x));
    return y;
}
__device__ __forceinline__ void cp_async16(void* dst, const void* src) {
    unsigned d = (unsigned)__cvta_generic_to_shared(dst);
    asm volatile("cp.async.cg.shared.global [%0], [%1], 16;"
                 :: "r"(d), "l"(src) : "memory");
}

// ---- packed f32x2 helpers (sm_100+) ----
typedef unsigned long long u64t;
__device__ __forceinline__ u64t pk2(float x, float y) {
    u64t r; asm("mov.b64 %0, {%1, %2};" : "=l"(r) : "f"(x), "f"(y)); return r;
}
__device__ __forceinline__ float2 up2(u64t v) {
    float2 r; asm("mov.b64 {%0, %1}, %2;" : "=f"(r.x), "=f"(r.y) : "l"(v));
    return r;
}
__device__ __forceinline__ u64t fma2_(u64t a, u64t b, u64t c) {
    u64t d; asm("fma.rn.f32x2 %0, %1, %2, %3;" : "=l"(d) : "l"(a), "l"(b), "l"(c));
    return d;
}
__device__ __forceinline__ u64t add2_(u64t a, u64t b) {
    u64t d; asm("add.rn.f32x2 %0, %1, %2;" : "=l"(d) : "l"(a), "l"(b)); return d;
}
__device__ __forceinline__ u64t mul2_(u64t a, u64t b) {
    u64t d; asm("mul.rn.f32x2 %0, %1, %2;" : "=l"(d) : "l"(a), "l"(b)); return d;
}
__device__ __forceinline__ u64t abs2_(u64t a) {
    u64t d; asm("and.b64 %0, %1, %2;" : "=l"(d)
                : "l"(a), "l"(0x7FFFFFFF7FFFFFFFULL)); return d;
}

__global__ __launch_bounds__(128, 4) void mlgru_kernel(
    const float* __restrict__ x, const float* __restrict__ hprev,
    const float* __restrict__ bf_, const float* __restrict__ bc_,
    const float* __restrict__ bg_, float* __restrict__ out, int half) {
    // A fragments: [mtile(8)][ktile(8)][lane(32)] -> uint4; warp-local.
    __shared__ uint4 qfrag[8][8][32];
    // B stage: double buffer of half-chunk units [mat(3)][ktl(4)][lane(32)]
    __shared__ uint4 bstage[2][3 * 128];

    const int tid = threadIdx.x;
    const int w = tid >> 5, l = tid & 31;
    const int q4 = l & 3;          // column group (phase 1) == tig (phase 2)
    const int rg = l >> 2;         // row-in-octet (phase 1) == g (phase 2)
    const int rowBlock = blockIdx.x * 128;

    // ---- prologue: stage unit 0 (ch0, kts 0-3); overlaps phase 1 ----
    #pragma unroll
    for (int m = 0; m < 3; m++)
        cp_async16(&bstage[0][m * 128 + tid],
                   g_wfrag + (m * 8) * 8 * 32 + tid);
    asm volatile("cp.async.commit_group;" ::: "memory");

    // sih[it]: 0.5*(maxabs/127) of local row it*8 + rg  (it = 2*mt + rh)
    float sih[4];

    // ------------- Phase 1: layernorm + quant (4-lane reductions) ----------
    {
        #pragma unroll 1
        for (int it = 0; it < 4; it++) {
            const int rl = w * 32 + it * 8 + rg;          // block-local row
            const float4* xr = (const float4*)(x + (size_t)(rowBlock + rl) * 128);
            u64t vp[16];
            #pragma unroll
            for (int j = 0; j < 8; j++) {
                const float4 v = xr[4 * j + q4];
                vp[2 * j]     = pk2(v.x, v.y);
                vp[2 * j + 1] = pk2(v.z, v.w);
            }

            u64t s1p = add2_(vp[0], vp[1]);
            #pragma unroll
            for (int k = 2; k < 16; k++) s1p = add2_(s1p, vp[k]);
            u64t s2p = mul2_(vp[0], vp[0]);
            #pragma unroll
            for (int k = 1; k < 16; k++) s2p = fma2_(vp[k], vp[k], s2p);
            float2 t1 = up2(s1p), t2 = up2(s2p);
            float s1 = t1.x + t1.y, s2 = t2.x + t2.y;

            #pragma unroll
            for (int m = 1; m <= 2; m <<= 1) {
                s1 += __shfl_xor_sync(0xffffffffu, s1, m);
                s2 += __shfl_xor_sync(0xffffffffu, s2, m);
            }
            const float mean = s1 * (1.f / 128.f);
            const float var  = s2 * (1.f / 128.f) - mean * mean;
            const float rstd = rsqrtf(var + 1e-8f);

            const u64t rs2 = pk2(rstd, rstd);
            const u64t nm2 = pk2(-mean * rstd, -mean * rstd);
            float mx = 0.f;
            #pragma unroll
            for (int k = 0; k < 16; k++) {
                const float2 a = up2(abs2_(fma2_(vp[k], rs2, nm2)));
                mx = fmaxf(mx, fmaxf(a.x, a.y));
            }
            #pragma unroll
            for (int m = 1; m <= 2; m <<= 1)
                mx = fmaxf(mx, __shfl_xor_sync(0xffffffffu, mx, m));

            const float s = __fdividef(127.f, mx);
            sih[it] = 0.5f * mx * (1.f / 127.f);

            const float aa = rstd * s;
            const u64t aa2 = pk2(aa, aa);
            const u64t bb2 = pk2(-mean * aa, -mean * aa);

            const int mt = rl >> 4, g8 = rl & 7, hi2 = (rl >> 3) & 1;
            #pragma unroll
            for (int j = 0; j < 8; j++) {        // kt == j
                #pragma unroll
                for (int p = 0; p < 2; p++) {
                    const float2 qv = up2(fma2_(vp[2 * j + p], aa2, bb2));
                    const unsigned u = __byte_perm(
                        __float_as_uint(rintf(qv.x)),
                        __float_as_uint(rintf(qv.y)), 0x7632);
                    const int idx8 = 2 * q4 + p;          // 0..7
                    const int tg   = idx8 & 3;
                    const int khi  = idx8 >> 2;
                    ((unsigned*)&qfrag[mt][j][(g8 << 2) | tg])[hi2 | (khi << 1)] = u;
                }
            }
        }
    }

    // ------------------- Phase 2: 3 ternary MMAs + gates -------------------
    const int g = rg, tig = q4;
    const int rbase = rowBlock + w * 32 + g;   // + mt*16 + rh*8

    #pragma unroll 1
    for (int ch = 0; ch < 8; ch++) {    // 16 output columns per chunk
        const int cbase = ch * 16 + tig * 4;

        float4 hp[2][2];
        float acc[3][2][2][4];
        #pragma unroll
        for (int m_ = 0; m_ < 3; m_++)
            #pragma unroll
            for (int a_ = 0; a_ < 2; a_++)
                #pragma unroll
                for (int t_ = 0; t_ < 2; t_++)
                    #pragma unroll
                    for (int e_ = 0; e_ < 4; e_++) acc[m_][a_][t_][e_] = 0.f;

        #pragma unroll
        for (int h = 0; h < 2; h++) {
            const int u = ch * 2 + h;
            // unit u resident (own copies); barrier -> all copies visible
            asm volatile("cp.async.wait_group 0;" ::: "memory");
            __syncthreads();
            // stage unit u+1 into the other buffer (readers finished above)
            if (u < 15) {
                const int un = u + 1;
                const int chn = un >> 1, hn = un & 1;
                #pragma unroll
                for (int m = 0; m < 3; m++)
                    cp_async16(&bstage[un & 1][m * 128 + tid],
                               g_wfrag + ((m * 8 + chn) * 8) * 32 +
                                   hn * 128 + tid);
                asm volatile("cp.async.commit_group;" ::: "memory");
            } else {
                asm volatile("cp.async.commit_group;" ::: "memory");
            }

            if (h == 0) {
                #pragma unroll
                for (int mt = 0; mt < 2; mt++)
                    #pragma unroll
                    for (int rh = 0; rh < 2; rh++)
                        hp[mt][rh] = *(const float4*)(hprev +
                            (size_t)(rbase + mt * 16 + rh * 8) * 128 + cbase);
            }

            const uint4* bb = &bstage[u & 1][l];
            #pragma unroll
            for (int ktl = 0; ktl < 4; ktl++) {
                const int kt = h * 4 + ktl;
                const uint4 A0 = qfrag[2 * w][kt][l];
                const uint4 A1 = qfrag[2 * w + 1][kt][l];
                #pragma unroll
                for (int mat = 0; mat < 3; mat++) {
                    const uint4 Bv = bb[mat * 128 + ktl * 32];
                    MMA_OP(acc[mat][0][0], A0, Bv.x, Bv.y);
                    MMA_OP(acc[mat][1][0], A1, Bv.x, Bv.y);
                    MMA_OP(acc[mat][0][1], A0, Bv.z, Bv.w);
                    MMA_OP(acc[mat][1][1], A1, Bv.z, Bv.w);
                }
            }
        }

        // ---- epilogue: 4 contiguous cols/thread, float4 stores ----
        const float4 bF = __ldg((const float4*)(bf_ + cbase));
        const float4 bC = __ldg((const float4*)(bc_ + cbase));
        const float4 bG = __ldg((const float4*)(bg_ + cbase));
        const float bFv[4] = {0.5f*bF.x, 0.5f*bF.y, 0.5f*bF.z, 0.5f*bF.w};
        const float bCv[4] = {0.5f*bC.x, 0.5f*bC.y, 0.5f*bC.z, 0.5f*bC.w};
        const float bGv[4] = {0.5f*bG.x, 0.5f*bG.y, 0.5f*bG.z, 0.5f*bG.w};

        #pragma unroll
        for (int mt = 0; mt < 2; mt++) {
            #pragma unroll
            for (int rh = 0; rh < 2; rh++) {
                const int row = rbase + mt * 16 + rh * 8;
                const float si = sih[2 * mt + rh];
                const float hpv[4] = {hp[mt][rh].x, hp[mt][rh].y,
                                      hp[mt][rh].z, hp[mt][rh].w};
                float ov[4], hv[4];
                #pragma unroll
                for (int c = 0; c < 4; c++) {
                    const int t_ = c >> 1, e_ = rh * 2 + (c & 1);
                    const float zf = fmaf(acc[0][mt][t_][e_], si, bFv[c]);
                    const float zc = fmaf(acc[1][mt][t_][e_], si, bCv[c]);
                    const float zg = fmaf(acc[2][mt][t_][e_], si, bGv[c]);
                    const float f  = fmaf(0.5f, tanh_ap(zf), 0.5f);
                    const float gg = fmaf(0.5f, tanh_ap(zg), 0.5f);
                    const float sc = fmaf(0.5f, tanh_ap(zc), 0.5f);
                    const float cv = (zc + zc) * sc;      // silu
                    const float h  = fmaf(f, hpv[c] - cv, cv);
                    hv[c] = h;
                    ov[c] = gg * h;
                }
                *(float4*)(out + (size_t)row * 128 + cbase) =
                    make_float4(ov[0], ov[1], ov[2], ov[3]);
                *(float4*)(out + (size_t)half + (size_t)row * 128 + cbase) =
                    make_float4(hv[0], hv[1], hv[2], hv[3]);
            }
        }
    }
}

extern "C" void kernel_launch(void* const* d_in, const int* in_sizes, int n_in,
                              void* d_out, int out_size) {
    const float* x  = (const float*)d_in[0];
    const float* h  = (const float*)d_in[1];
    const float* Wf = (const float*)d_in[2];
    const float* Wc = (const float*)d_in[3];
    const float* Wg = (const float*)d_in[4];
    const float* bf = (const float*)d_in[5];
    const float* bc = (const float*)d_in[6];
    const float* bg = (const float*)d_in[7];
    float* out = (float*)d_out;

    prep_kernel<<<48, 128>>>(Wf, Wc, Wg);

    const int rows = in_sizes[0] / 128;      // 262144
    const int blocks = rows / 128;           // 2048
    const int half = out_size / 2;
    mlgru_kernel<<<blocks, 128>>>(x, h, bf, bc, bg, out, half);
}